// round 9
// baseline (speedup 1.0000x reference)
#include <cuda_runtime.h>
#include <cuda_bf16.h>

// Problem constants
constexpr int B = 4, C = 32, H = 720, W = 720;
constexpr int HW = H * W;              // 518400

// Produce units: 2 rows x full W channel-sum slabs
constexpr int PROWS = 2;
constexpr int NPROD_PB = H / PROWS;    // 360
constexpr int NPROD = B * NPROD_PB;    // 1440

// Consume units: 8 rows x 180 cols output tiles
constexpr int TH = 8, TWF = 180;
constexpr int NBANDS = H / TH;         // 90
constexpr int NCOLT = W / TWF;         // 4
constexpr int NCONS_PB = NBANDS * NCOLT; // 360
constexpr int NCONS = B * NCONS_PB;    // 1440

constexpr int SROWS = TH + 10;   // 18 s rows (d needs ±1 rows, each d row ±4 diag)
constexpr int DROWS = TH + 2;    // 10 d rows
constexpr int SW = TWF + 8;      // 188

constexpr int NBLOCKS = 888;     // 148 SMs x ~6 blocks

// Scratch + coordination state (zero-initialized; self-reset at kernel end)
__device__ float g_s[B * HW];
__device__ int g_prod_ticket;
__device__ int g_cons_ticket;
__device__ int g_prog[B];        // per-batch produce progress (units committed, ordered)
__device__ int g_done;

// ---- produce: s rows [2r, 2r+2) of batch b = sum_c x[b,c,...] ----
__device__ __forceinline__ void produce(const float* __restrict__ x, int t, int tid) {
    int b = t / NPROD_PB;
    int r = t % NPROD_PB;
    const float4* xb = reinterpret_cast<const float4*>(x + (size_t)b * C * HW);
    float4* sb = reinterpret_cast<float4*>(g_s + (size_t)b * HW);
    int base = r * (PROWS * W / 4);                 // r * 360
    for (int i = tid; i < PROWS * W / 4; i += 256) {
        int idx = base + i;
        float4 acc = make_float4(0.f, 0.f, 0.f, 0.f);
        #pragma unroll
        for (int c = 0; c < C; c++) {
            float4 v = __ldcs(&xb[(size_t)c * (HW / 4) + idx]);
            acc.x += v.x; acc.y += v.y; acc.z += v.z; acc.w += v.w;
        }
        sb[idx] = acc;
    }
    __syncthreads();                                // all s stores done
    if (tid == 0) {
        // ordered commit within batch
        while (atomicAdd(&g_prog[b], 0) != r) { __nanosleep(40); }
        __threadfence();                            // publish s before bumping prog
        atomicExch(&g_prog[b], r + 1);
    }
}

// ---- consume: out tile (b, band, colchunk): 9-tap diag avg + 3-tap conv ----
__device__ __forceinline__ void consume(const float* __restrict__ cw,
                                        float* __restrict__ out, int v, int tid,
                                        float (*s_sm)[SW], float (*d_sm)[SW],
                                        float* sw) {
    int b = v / NCONS_PB;
    int rem = v % NCONS_PB;
    int band = rem / NCOLT;
    int col  = rem % NCOLT;
    int h0 = band * TH;
    int w0 = col * TWF;
    const float* sb = g_s + (size_t)b * HW;

    // w2 reduction into smem (L2-hit reads)
    if (tid < C * 3) {
        int o = tid / 3, kh = tid % 3;
        float acc = 0.f;
        #pragma unroll
        for (int i = 0; i < C; i++) acc += __ldg(&cw[o * (C * 3) + i * 3 + kh]);
        sw[tid] = acc;
    }

    // stage 1: s tile [h0-5 .. h0+12] x [w0-4 .. w0+183]
    for (int t = tid; t < SROWS * (SW / 4); t += 256) {
        int i = t / (SW / 4);
        int vv = t % (SW / 4);
        int gr = h0 - 5 + i;
        int gc = w0 - 4 + 4 * vv;
        float4 val = make_float4(0.f, 0.f, 0.f, 0.f);
        if (gr >= 0 && gr < H && gc >= 0 && gc + 3 < W)
            val = *reinterpret_cast<const float4*>(sb + gr * W + gc);
        *reinterpret_cast<float4*>(&s_sm[i][4 * vv]) = val;
    }
    __syncthreads();

    // stage 2: d rows h0-1 .. h0+8
    for (int t = tid; t < DROWS * TWF; t += 256) {
        int k  = t / TWF;
        int cc = t % TWF;
        int r = h0 - 1 + k;
        float acc = 0.f;
        if (r >= 0 && r < H) {
            #pragma unroll
            for (int j = 0; j < 9; j++) acc += s_sm[k + j][cc + j];
            acc *= (1.0f / 9.0f);
        }
        d_sm[k][cc] = acc;
    }
    __syncthreads();

    // stage 3: out
    for (int t = tid; t < TH * (TWF / 4); t += 256) {
        int k2 = t / (TWF / 4);
        int cf = t % (TWF / 4);
        int h  = h0 + k2;
        int wc = w0 + 4 * cf;
        float4 d0 = *reinterpret_cast<const float4*>(&d_sm[k2    ][4 * cf]);
        float4 d1 = *reinterpret_cast<const float4*>(&d_sm[k2 + 1][4 * cf]);
        float4 d2 = *reinterpret_cast<const float4*>(&d_sm[k2 + 2][4 * cf]);
        float* op = out + (size_t)b * C * HW + h * W + wc;
        #pragma unroll
        for (int o = 0; o < C; o++) {
            float a0 = sw[3 * o], a1 = sw[3 * o + 1], a2 = sw[3 * o + 2];
            float4 rv;
            rv.x = a0 * d0.x + a1 * d1.x + a2 * d2.x;
            rv.y = a0 * d0.y + a1 * d1.y + a2 * d2.y;
            rv.z = a0 * d0.z + a1 * d1.z + a2 * d2.z;
            rv.w = a0 * d0.w + a1 * d1.w + a2 * d2.w;
            __stcs(reinterpret_cast<float4*>(op + (size_t)o * HW), rv);
        }
    }
    __syncthreads();   // smem reuse safety for next unit
}

__device__ __forceinline__ int cons_need(int v) {
    int band = (v % NCONS_PB) / NCOLT;
    int need = 4 * band + 7;
    return need > NPROD_PB ? NPROD_PB : need;
}

__global__ __launch_bounds__(256) void k_pipeline(const float* __restrict__ x,
                                                  const float* __restrict__ cw,
                                                  float* __restrict__ out) {
    __shared__ __align__(16) float s_sm[SROWS][SW];
    __shared__ __align__(16) float d_sm[DROWS][SW];
    __shared__ float sw[C * 3];
    __shared__ int sh_action, sh_param, sh_pend;

    int tid = threadIdx.x;
    if (tid == 0) sh_pend = -1;
    __syncthreads();

    for (;;) {
        if (tid == 0) {
            int a = -1, p = 0;
            int pd = sh_pend;
            // acquire a pending consume ticket if we have none
            if (pd == -1) {
                int u = atomicAdd(&g_cons_ticket, 1);
                if (u < NCONS) { sh_pend = pd = u; }
                else           { sh_pend = pd = -2; }   // consume drained
            }
            // pending consume ready? (non-blocking)
            if (pd >= 0) {
                int b = pd / NCONS_PB;
                if (atomicAdd(&g_prog[b], 0) >= cons_need(pd)) {
                    __threadfence();                    // acquire s
                    a = 1; p = pd; sh_pend = -1;
                }
            }
            if (a < 0) {
                int t = atomicAdd(&g_prod_ticket, 1);
                if (t < NPROD) { a = 0; p = t; }
                else if (pd >= 0) {
                    // produce drained: blocking wait on pending consume
                    int b = pd / NCONS_PB;
                    int need = cons_need(pd);
                    while (atomicAdd(&g_prog[b], 0) < need) { __nanosleep(60); }
                    __threadfence();
                    a = 1; p = pd; sh_pend = -1;
                } else {
                    a = 3;                              // all done
                }
            }
            sh_action = a; sh_param = p;
        }
        __syncthreads();
        int a = sh_action, p = sh_param;
        if (a == 3) break;
        if (a == 0) produce(x, p, tid);
        else        consume(cw, out, p, tid, s_sm, d_sm, sw);
        __syncthreads();
    }

    // last block resets coordination state for the next (graph-replayed) launch
    if (tid == 0) {
        int d = atomicAdd(&g_done, 1);
        if (d == NBLOCKS - 1) {
            g_prod_ticket = 0;
            g_cons_ticket = 0;
            #pragma unroll
            for (int i = 0; i < B; i++) g_prog[i] = 0;
            g_done = 0;
            __threadfence();
        }
    }
}

extern "C" void kernel_launch(void* const* d_in, const int* in_sizes, int n_in,
                              void* d_out, int out_size) {
    const float* x  = (const float*)d_in[0];   // (4,32,720,720)
    const float* cw = (const float*)d_in[1];   // (32,32,3,1)
    float* out = (float*)d_out;                // (4,32,720,720)

    k_pipeline<<<NBLOCKS, 256>>>(x, cw, out);
}

// round 10
// speedup vs baseline: 5.7116x; 5.7116x over previous
#include <cuda_runtime.h>
#include <cuda_bf16.h>

// Problem constants
constexpr int B = 4, C = 32, H = 720, W = 720;
constexpr int HW = H * W;              // 518400
constexpr int BHW = B * HW;            // 2073600

// Tiling for fused diag+conv kernel
constexpr int TH  = 8;     // output rows per block
constexpr int TWF = 360;   // output cols per block (W/2)
constexpr int SROWS = TH + 10;   // 18 s rows (halo: d needs ±1 rows, each d row ±4 diag)
constexpr int DROWS = TH + 2;    // 10 d rows
constexpr int SW  = 368;   // smem row width (360 + 8 halo cols)

// Scratch (no cudaMalloc allowed)
__device__ float g_s[BHW];       // channel sum

// K1: s[b,h,w] = sum_c x[b,c,h,w]  (float4 over w, streaming loads,
// explicitly batched 8-deep for MLP)
__global__ __launch_bounds__(256, 8) void k_csum(const float* __restrict__ x) {
    int idx = blockIdx.x * blockDim.x + threadIdx.x;   // over BHW/4
    if (idx >= BHW / 4) return;
    int base = idx * 4;
    int b = base / HW;
    int hw = base % HW;
    const float4* xp = reinterpret_cast<const float4*>(x + (size_t)b * C * HW + hw);

    float4 acc = make_float4(0.f, 0.f, 0.f, 0.f);
    #pragma unroll
    for (int c0 = 0; c0 < C; c0 += 8) {
        float4 v[8];
        #pragma unroll
        for (int j = 0; j < 8; j++)
            v[j] = __ldcs(&xp[(size_t)(c0 + j) * (HW / 4)]);   // 8 loads in flight
        #pragma unroll
        for (int j = 0; j < 8; j++) {
            acc.x += v[j].x; acc.y += v[j].y; acc.z += v[j].z; acc.w += v[j].w;
        }
    }
    reinterpret_cast<float4*>(g_s)[idx] = acc;          // s stays L2-resident
}

// K2 (fused): w2 reduction + 9-tap diagonal average of s + 3-tap broadcast conv
__global__ __launch_bounds__(256) void k_fused(const float* __restrict__ cw,
                                               float* __restrict__ out) {
    __shared__ __align__(16) float s_sm[SROWS][SW];
    __shared__ __align__(16) float d_sm[DROWS][SW];
    __shared__ float sw[C * 3];

    int tid = threadIdx.x;
    // Per-block w2 reduction: w2[o,kh] = sum_i conv_w[o,i,kh,0]  (L2-hit reads)
    if (tid < C * 3) {
        int o = tid / 3, kh = tid % 3;
        float acc = 0.f;
        #pragma unroll
        for (int i = 0; i < C; i++) acc += __ldg(&cw[o * (C * 3) + i * 3 + kh]);
        sw[tid] = acc;
    }

    int b  = blockIdx.z;
    int h0 = blockIdx.y * TH;
    int w0 = blockIdx.x * TWF;
    const float* sb = g_s + (size_t)b * HW;

    // Stage 1: load s tile [h0-5 .. h0+TH+4] x [w0-4 .. w0+TWF+3] (zero pad OOB)
    for (int t = tid; t < SROWS * (SW / 4); t += 256) {
        int i = t / (SW / 4);
        int v = t % (SW / 4);
        int gr = h0 - 5 + i;
        int gc = w0 - 4 + 4 * v;       // 16B aligned (w0 % 4 == 0)
        float4 val = make_float4(0.f, 0.f, 0.f, 0.f);
        if (gr >= 0 && gr < H && gc >= 0 && gc + 3 < W)
            val = *reinterpret_cast<const float4*>(sb + gr * W + gc);
        *reinterpret_cast<float4*>(&s_sm[i][4 * v]) = val;
    }
    __syncthreads();

    // Stage 2: d tile rows r = h0-1 .. h0+TH (zero if r outside image)
    for (int t = tid; t < DROWS * TWF; t += 256) {
        int k  = t / TWF;
        int cc = t % TWF;
        int r = h0 - 1 + k;
        float acc = 0.f;
        if (r >= 0 && r < H) {
            #pragma unroll
            for (int j = 0; j < 9; j++) acc += s_sm[k + j][cc + j];
            acc *= (1.0f / 9.0f);
        }
        d_sm[k][cc] = acc;
    }
    __syncthreads();

    // Stage 3: out[b,o,h,w] = sum_kh w2[o,kh] * d[h-1+kh, w], streaming stores
    for (int t = tid; t < TH * (TWF / 4); t += 256) {
        int k2 = t / (TWF / 4);
        int cf = t % (TWF / 4);
        int h  = h0 + k2;
        int wc = w0 + 4 * cf;

        float4 d0 = *reinterpret_cast<const float4*>(&d_sm[k2    ][4 * cf]);
        float4 d1 = *reinterpret_cast<const float4*>(&d_sm[k2 + 1][4 * cf]);
        float4 d2 = *reinterpret_cast<const float4*>(&d_sm[k2 + 2][4 * cf]);

        float* op = out + (size_t)b * C * HW + h * W + wc;
        #pragma unroll
        for (int o = 0; o < C; o++) {
            float a0 = sw[3 * o], a1 = sw[3 * o + 1], a2 = sw[3 * o + 2];
            float4 rv;
            rv.x = a0 * d0.x + a1 * d1.x + a2 * d2.x;
            rv.y = a0 * d0.y + a1 * d1.y + a2 * d2.y;
            rv.z = a0 * d0.z + a1 * d1.z + a2 * d2.z;
            rv.w = a0 * d0.w + a1 * d1.w + a2 * d2.w;
            __stcs(reinterpret_cast<float4*>(op + (size_t)o * HW), rv);
        }
    }
}

extern "C" void kernel_launch(void* const* d_in, const int* in_sizes, int n_in,
                              void* d_out, int out_size) {
    const float* x  = (const float*)d_in[0];   // (4,32,720,720)
    const float* cw = (const float*)d_in[1];   // (32,32,3,1)
    float* out = (float*)d_out;                // (4,32,720,720)

    {
        int n = BHW / 4;
        k_csum<<<(n + 255) / 256, 256>>>(x);
    }

    dim3 grid(W / TWF, H / TH, B);             // (2, 90, 4) = 720 blocks
    k_fused<<<grid, 256>>>(cw, out);
}

// round 11
// speedup vs baseline: 5.8892x; 1.0311x over previous
#include <cuda_runtime.h>
#include <cuda_bf16.h>

// Problem constants
constexpr int B = 4, C = 32, H = 720, W = 720;
constexpr int HW = H * W;              // 518400
constexpr int BHW = B * HW;            // 2073600

// Tiling for fused diag+conv kernel
constexpr int TH  = 8;     // output rows per block
constexpr int TWF = 360;   // output cols per block (W/2)
constexpr int SROWS = TH + 10;   // 18 s rows (halo: d needs ±1 rows, each d row ±4 diag)
constexpr int DROWS = TH + 2;    // 10 d rows
constexpr int SW  = 368;   // smem row width (360 + 8 halo cols)
constexpr int NDIAG = TWF + DROWS - 1;  // 369 diagonals in the d tile

// Scratch (no cudaMalloc allowed)
__device__ float g_s[BHW];       // channel sum

// K1: s[b,h,w] = sum_c x[b,c,h,w]  (float4 over w, streaming loads)
__global__ __launch_bounds__(256) void k_csum(const float* __restrict__ x) {
    int idx = blockIdx.x * blockDim.x + threadIdx.x;   // over BHW/4
    if (idx >= BHW / 4) return;
    int base = idx * 4;
    int b = base / HW;
    int hw = base % HW;
    const float4* xp = reinterpret_cast<const float4*>(x + (size_t)b * C * HW + hw);
    float4 acc = make_float4(0.f, 0.f, 0.f, 0.f);
    #pragma unroll
    for (int c = 0; c < C; c++) {
        float4 v = __ldcs(&xp[(size_t)c * (HW / 4)]);   // evict-first: x has no reuse
        acc.x += v.x; acc.y += v.y; acc.z += v.z; acc.w += v.w;
    }
    reinterpret_cast<float4*>(g_s)[idx] = acc;          // s stays L2-resident
}

// K2 (fused): w2 reduction + 9-tap diagonal average (sliding-window along the
// diagonal: 2 LDS/element instead of 9) + 3-tap broadcast conv
__global__ __launch_bounds__(256) void k_fused(const float* __restrict__ cw,
                                               float* __restrict__ out) {
    __shared__ __align__(16) float s_sm[SROWS][SW];
    __shared__ __align__(16) float d_sm[DROWS][SW];
    __shared__ float sw[C * 3];

    int tid = threadIdx.x;
    // Per-block w2 reduction: w2[o,kh] = sum_i conv_w[o,i,kh,0]  (L2-hit reads)
    if (tid < C * 3) {
        int o = tid / 3, kh = tid % 3;
        float acc = 0.f;
        #pragma unroll
        for (int i = 0; i < C; i++) acc += __ldg(&cw[o * (C * 3) + i * 3 + kh]);
        sw[tid] = acc;
    }

    int b  = blockIdx.z;
    int h0 = blockIdx.y * TH;
    int w0 = blockIdx.x * TWF;
    const float* sb = g_s + (size_t)b * HW;

    // Stage 1: load s tile [h0-5 .. h0+TH+4] x [w0-4 .. w0+TWF+3] (zero pad OOB)
    for (int t = tid; t < SROWS * (SW / 4); t += 256) {
        int i = t / (SW / 4);
        int v = t % (SW / 4);
        int gr = h0 - 5 + i;
        int gc = w0 - 4 + 4 * v;       // 16B aligned (w0 % 4 == 0)
        float4 val = make_float4(0.f, 0.f, 0.f, 0.f);
        if (gr >= 0 && gr < H && gc >= 0 && gc + 3 < W)
            val = *reinterpret_cast<const float4*>(sb + gr * W + gc);
        *reinterpret_cast<float4*>(&s_sm[i][4 * v]) = val;
    }
    __syncthreads();

    // Stage 2: d tile via diagonal sliding window.
    // d[k][cc] = (1/9) * sum_{j=0..8} s_sm[k+j][cc+j]   (image row r = h0-1+k)
    // Along the diagonal (k,cc) -> (k+1,cc+1):
    //   D += s_sm[k+8][cc+9] - s_sm[k-1][cc]
    for (int t = tid; t < NDIAG; t += 256) {
        int c0 = t - (DROWS - 1);                  // -9 .. 359
        int k0 = c0 < 0 ? -c0 : 0;                 // first k with cc >= 0
        int k1 = TWF - 1 - c0;                     // last k with cc <= 359
        if (k1 > DROWS - 1) k1 = DROWS - 1;
        int cc = c0 + k0;

        float D = 0.f;
        #pragma unroll
        for (int j = 0; j < 9; j++) D += s_sm[k0 + j][cc + j];
        {
            int r = h0 - 1 + k0;
            d_sm[k0][cc] = (r >= 0 && r < H) ? D * (1.0f / 9.0f) : 0.f;
        }
        for (int k = k0 + 1; k <= k1; k++) {
            D += s_sm[k + 8][cc + 9] - s_sm[k - 1][cc];
            cc++;
            int r = h0 - 1 + k;
            d_sm[k][cc] = (r >= 0 && r < H) ? D * (1.0f / 9.0f) : 0.f;
        }
    }
    __syncthreads();

    // Stage 3: out[b,o,h,w] = sum_kh w2[o,kh] * d[h-1+kh, w], streaming stores
    for (int t = tid; t < TH * (TWF / 4); t += 256) {
        int k2 = t / (TWF / 4);
        int cf = t % (TWF / 4);
        int h  = h0 + k2;
        int wc = w0 + 4 * cf;

        float4 d0 = *reinterpret_cast<const float4*>(&d_sm[k2    ][4 * cf]);
        float4 d1 = *reinterpret_cast<const float4*>(&d_sm[k2 + 1][4 * cf]);
        float4 d2 = *reinterpret_cast<const float4*>(&d_sm[k2 + 2][4 * cf]);

        float* op = out + (size_t)b * C * HW + h * W + wc;
        #pragma unroll
        for (int o = 0; o < C; o++) {
            float a0 = sw[3 * o], a1 = sw[3 * o + 1], a2 = sw[3 * o + 2];
            float4 rv;
            rv.x = a0 * d0.x + a1 * d1.x + a2 * d2.x;
            rv.y = a0 * d0.y + a1 * d1.y + a2 * d2.y;
            rv.z = a0 * d0.z + a1 * d1.z + a2 * d2.z;
            rv.w = a0 * d0.w + a1 * d1.w + a2 * d2.w;
            __stcs(reinterpret_cast<float4*>(op + (size_t)o * HW), rv);
        }
    }
}

extern "C" void kernel_launch(void* const* d_in, const int* in_sizes, int n_in,
                              void* d_out, int out_size) {
    const float* x  = (const float*)d_in[0];   // (4,32,720,720)
    const float* cw = (const float*)d_in[1];   // (32,32,3,1)
    float* out = (float*)d_out;                // (4,32,720,720)

    {
        int n = BHW / 4;
        k_csum<<<(n + 255) / 256, 256>>>(x);
    }

    dim3 grid(W / TWF, H / TH, B);             // (2, 90, 4) = 720 blocks
    k_fused<<<grid, 256>>>(cw, out);
}